// round 15
// baseline (speedup 1.0000x reference)
#include <cuda_runtime.h>
#include <cuda_bf16.h>
#include <math.h>

#define BATCH 2048
#define IN_C  256
#define OUT_C 256
#define NSPL  5
#define NINT  16

typedef unsigned long long ull;

// params: float4 = {b3*log2e, b4, b2*ln2, b1*g*ln2}, scalar = b5*g, layout [i][o]
__device__ float4 g_par4[IN_C * OUT_C];
__device__ float  g_par1[IN_C * OUT_C];
// per-batch compacted active list: (x, i*256 as int bits), padded to multiple of 8
__device__ float2 g_act[BATCH * IN_C];
__device__ int    g_cnt[BATCH];

__device__ __forceinline__ float ex2f(float x) {
    float r; asm("ex2.approx.f32 %0, %1;" : "=f"(r) : "f"(x)); return r;
}
__device__ __forceinline__ float lg2f(float x) {
    float r; asm("lg2.approx.f32 %0, %1;" : "=f"(r) : "f"(x)); return r;
}
__device__ __forceinline__ ull pk2(float v) {
    unsigned u = __float_as_uint(v);
    return (((ull)u) << 32) | u;
}

#define FMA2(o,a,b,c) asm("fma.rn.f32x2 %0, %1, %2, %3;" : "=l"(o) : "l"(a), "l"(b), "l"(c))
#define ADD2(o,a,b)   asm("add.rn.f32x2 %0, %1, %2;"     : "=l"(o) : "l"(a), "l"(b))

// Merged pre-pass:
//   blocks [0,256):   spline params — block p = o-row p, thread = i.
//                     Coalesced reads; scattered (non-blocking) writes.
//   blocks [256,512): per-batch compaction of active x.
__global__ void __launch_bounds__(256)
kan_pre(const float* __restrict__ x,
        const float* __restrict__ w,
        const float* __restrict__ raw_gamma,
        const float* __restrict__ breaks,
        const float* __restrict__ coefs,
        const float* __restrict__ mu_p,
        const float* __restrict__ sigma_p) {
    if (blockIdx.x < 256) {
        __shared__ float brk_s[NSPL][NINT + 1];
        __shared__ float cf_s[NSPL * NINT * 4];
        int tid = threadIdx.x;
        for (int j = tid; j < NSPL * (NINT + 1); j += 256)
            brk_s[j / (NINT + 1)][j % (NINT + 1)] = breaks[j];
        for (int j = tid; j < NSPL * NINT * 4; j += 256)
            cf_s[j] = coefs[j];
        __syncthreads();

        int o = blockIdx.x;                  // one o-row per block
        int i = tid;                         // one i per thread
        float mu = *mu_p, sigma = *sigma_p;

        float wv = w[o * IN_C + i];          // coalesced
        wv = fminf(fmaxf(wv, 5.5f), 35.5f);
        float wn = (wv - mu) / sigma;

        float b[NSPL];
#pragma unroll
        for (int s = 0; s < NSPL; s++) {
            float lo  = brk_s[s][0];
            float hib = brk_s[s][NINT] - 1e-6f;
            float wc  = fminf(fmaxf(wn, lo), hib);
            int kk = 0;
#pragma unroll
            for (int q = 1; q <= NINT; q++) kk += (brk_s[s][q] <= wc) ? 1 : 0;
            if (kk > NINT - 1) kk = NINT - 1;
            float t = wc - brk_s[s][kk];
            const float* a = &cf_s[(s * NINT + kk) * 4];
            b[s] = ((a[0] * t + a[1]) * t + a[2]) * t + a[3];
        }

        float rg = raw_gamma[o * IN_C + i];  // coalesced
        float g = fmaxf(rg, 0.0f) + log1pf(expf(-fabsf(rg)));
        g *= (1.0f / (float)OUT_C);

        const float LN2 = 0.69314718055994530942f;
        const float L2E = 1.44269504088896340736f;
        // scattered stores (fire-and-forget; ~4MB of L2 write sectors total)
        g_par4[i * OUT_C + o] = make_float4(b[2] * L2E, b[3], b[1] * LN2, b[0] * g * LN2);
        g_par1[i * OUT_C + o] = b[4] * g;
    } else {
        int wrp = threadIdx.x >> 5, lane = threadIdx.x & 31;
        int b = (blockIdx.x - 256) * 8 + wrp;
        const float* xb = x + b * IN_C;
        int cnt = 0;
#pragma unroll
        for (int h = 0; h < IN_C / 32; h++) {
            int il = h * 32 + lane;
            float xv = xb[il];
            bool act = xv > 0.0f;
            unsigned m = __ballot_sync(0xffffffffu, act);
            int pos = __popc(m & ((1u << lane) - 1));
            if (act) g_act[b * IN_C + cnt + pos] =
                         make_float2(xv, __int_as_float(il << 8));
            cnt += __popc(m);
        }
        int padded = (cnt + 7) & ~7;           // pad to 8 for unrolled main loop
        if (lane < padded - cnt)
            g_act[b * IN_C + cnt + lane] = make_float2(0.0f, __int_as_float(0));
        if (lane == 0) g_cnt[b] = padded;
    }
}

// Packed exp2 for a pair of chains: E{0,1} = 2^T{0,1}, T >= 0, f32x2 FMA path.
// Degree-5 poly on f in [-0.5,0.5]; abs err ~2.4e-6 (tolerance 1e-3).
#define EX2PAIR(T0, T1, E0, E1) do {                                        \
    ull _t2, _k2, _u2, _f2, _r2;                                            \
    asm("mov.b64 %0, {%1,%2};" : "=l"(_t2)                                  \
        : "r"(__float_as_uint(T0)), "r"(__float_as_uint(T1)));              \
    ADD2(_k2, _t2, cM2);                                                    \
    ADD2(_u2, _k2, cNM2);          /* k - MAGIC = round(t) */               \
    FMA2(_f2, _u2, cNONE2, _t2);   /* f = t - round(t), in [-0.5,0.5] */    \
    _r2 = cC1;                                                              \
    FMA2(_r2, _r2, _f2, cC2);                                               \
    FMA2(_r2, _r2, _f2, cC3);                                               \
    FMA2(_r2, _r2, _f2, cC4);                                               \
    FMA2(_r2, _r2, _f2, cC5);                                               \
    FMA2(_r2, _r2, _f2, cC6);                                               \
    unsigned _kl, _kh, _rl, _rh;                                            \
    asm("mov.b64 {%0,%1}, %2;" : "=r"(_kl), "=r"(_kh) : "l"(_k2));          \
    asm("mov.b64 {%0,%1}, %2;" : "=r"(_rl), "=r"(_rh) : "l"(_r2));          \
    (E0) = __uint_as_float(_rl + (_kl << 23));                              \
    (E1) = __uint_as_float(_rh + (_kh << 23));                              \
} while (0)

// Chain tail after e = exp(b3*x); zero-x padding contributes exactly 0:
// e=1 -> |e-1|=0 -> lg2=-inf -> ex2=0 -> lgA=0 -> lgB=0.
#define TAIL(XV, E, P, C5, A, B) do {                                       \
    float _lb = lg2f(fabsf((E) - 1.0f));                                    \
    float _pw = ex2f((P).y * _lb);                                          \
    float _lA = lg2f(_pw + 1.0f);                                           \
    float _lB = lg2f(fmaf((P).z, _lA, 1.0f));                               \
    (A) = fmaf((P).w, _lB, (A));                                            \
    (B) = fmaf((C5), (XV), (B));                                            \
} while (0)

// One pair of chains: param loads, t-pair, packed exp, tails.
#define PAIR(XA, IA, XB, IB, Aa, Ba, Ab, Bb) do {                           \
    int _ia = __float_as_int(IA), _ib = __float_as_int(IB);                 \
    float4 _Pa = __ldg(p4 + _ia);                                           \
    float4 _Pb = __ldg(p4 + _ib);                                           \
    float _ca = __ldg(p1 + _ia);                                            \
    float _cb = __ldg(p1 + _ib);                                            \
    float _ta = _Pa.x * (XA), _tb = _Pb.x * (XB);                           \
    float _ea, _eb;                                                         \
    EX2PAIR(_ta, _tb, _ea, _eb);                                            \
    TAIL((XA), _ea, _Pa, _ca, Aa, Ba);                                      \
    TAIL((XB), _eb, _Pb, _cb, Ab, Bb);                                      \
} while (0)

__global__ void __launch_bounds__(256, 7)
kan_main(float* __restrict__ out) {
    int lane = threadIdx.x & 31;
    int wrp  = threadIdx.x >> 5;
    int b    = blockIdx.x * 8 + wrp;         // one batch per warp
    int o    = blockIdx.y * 32 + lane;       // one output per lane

    const float4* __restrict__ p4 = g_par4 + o;
    const float*  __restrict__ p1 = g_par1 + o;
    const float4* __restrict__ ap = (const float4*)(g_act + b * IN_C);

    const ull cM2    = pk2(12582912.0f);     // 1.5*2^23
    const ull cNM2   = pk2(-12582912.0f);
    const ull cNONE2 = pk2(-1.0f);
    const ull cC1    = pk2(1.33335581e-3f);
    const ull cC2    = pk2(9.61812911e-3f);
    const ull cC3    = pk2(5.55041087e-2f);
    const ull cC4    = pk2(2.40226507e-1f);
    const ull cC5    = pk2(6.93147181e-1f);
    const ull cC6    = pk2(1.0f);

    int cnt = g_cnt[b];                      // multiple of 8
    float A0 = 0.f, A1 = 0.f, A2 = 0.f, A3 = 0.f;
    float B0 = 0.f, B1 = 0.f, B2 = 0.f, B3 = 0.f;

    for (int n = 0; n < cnt; n += 8) {
        int h = n >> 1;
        float4 e01 = __ldg(ap + h);
        float4 e23 = __ldg(ap + h + 1);
        float4 e45 = __ldg(ap + h + 2);
        float4 e67 = __ldg(ap + h + 3);
        PAIR(e01.x, e01.y, e01.z, e01.w, A0, B0, A1, B1);
        PAIR(e23.x, e23.y, e23.z, e23.w, A2, B2, A3, B3);
        PAIR(e45.x, e45.y, e45.z, e45.w, A0, B0, A1, B1);
        PAIR(e67.x, e67.y, e67.z, e67.w, A2, B2, A3, B3);
    }

    float y  = ((A0 + A1) + (A2 + A3)) + ((B0 + B1) + (B2 + B3));
    float sp = fmaxf(y, 0.0f) + log1pf(expf(-fabsf(y)));
    out[b * OUT_C + o] = sp;
}

extern "C" void kernel_launch(void* const* d_in, const int* in_sizes, int n_in,
                              void* d_out, int out_size) {
    const float* x         = (const float*)d_in[0];
    const float* w         = (const float*)d_in[1];
    const float* raw_gamma = (const float*)d_in[2];
    const float* breaks    = (const float*)d_in[3];
    const float* coefs     = (const float*)d_in[4];
    const float* mu        = (const float*)d_in[5];
    const float* sigma     = (const float*)d_in[6];
    float* out = (float*)d_out;

    kan_pre<<<512, 256>>>(x, w, raw_gamma, breaks, coefs, mu, sigma);

    dim3 grid(BATCH / 8, OUT_C / 32);
    kan_main<<<grid, 256>>>(out);
}

// round 17
// speedup vs baseline: 1.4166x; 1.4166x over previous
#include <cuda_runtime.h>
#include <cuda_bf16.h>
#include <math.h>

#define BATCH 2048
#define IN_C  256
#define OUT_C 256
#define NSPL  5
#define NINT  16

typedef unsigned long long ull;

// params: float4 = {b3*log2e, b4, b2*ln2, b1*g*ln2}, scalar = b5*g, layout [i][o]
__device__ float4 g_par4[IN_C * OUT_C];
__device__ float  g_par1[IN_C * OUT_C];
// per-batch compacted active list: (x, i*256 as int bits), padded to multiple of 8
__device__ float2 g_act[BATCH * IN_C];
__device__ int    g_cnt[BATCH];

__device__ __forceinline__ float ex2f(float x) {
    float r; asm("ex2.approx.f32 %0, %1;" : "=f"(r) : "f"(x)); return r;
}
__device__ __forceinline__ float lg2f(float x) {
    float r; asm("lg2.approx.f32 %0, %1;" : "=f"(r) : "f"(x)); return r;
}
__device__ __forceinline__ ull pk2(float v) {
    unsigned u = __float_as_uint(v);
    return (((ull)u) << 32) | u;
}

#define FMA2(o,a,b,c) asm("fma.rn.f32x2 %0, %1, %2, %3;" : "=l"(o) : "l"(a), "l"(b), "l"(c))
#define ADD2(o,a,b)   asm("add.rn.f32x2 %0, %1, %2;"     : "=l"(o) : "l"(a), "l"(b))

// Merged pre-pass:
//   blocks [0,256):   spline params — block p = o-row p, thread = i.
//                     Coalesced reads; scattered (non-blocking) writes.
//   blocks [256,512): per-batch compaction of active x.
__global__ void __launch_bounds__(256)
kan_pre(const float* __restrict__ x,
        const float* __restrict__ w,
        const float* __restrict__ raw_gamma,
        const float* __restrict__ breaks,
        const float* __restrict__ coefs,
        const float* __restrict__ mu_p,
        const float* __restrict__ sigma_p) {
    if (blockIdx.x < 256) {
        __shared__ float brk_s[NSPL][NINT + 1];
        __shared__ float cf_s[NSPL * NINT * 4];
        int tid = threadIdx.x;
        for (int j = tid; j < NSPL * (NINT + 1); j += 256)
            brk_s[j / (NINT + 1)][j % (NINT + 1)] = breaks[j];
        for (int j = tid; j < NSPL * NINT * 4; j += 256)
            cf_s[j] = coefs[j];
        __syncthreads();

        int o = blockIdx.x;                  // one o-row per block
        int i = tid;                         // one i per thread
        float mu = *mu_p, sigma = *sigma_p;

        float wv = w[o * IN_C + i];          // coalesced
        wv = fminf(fmaxf(wv, 5.5f), 35.5f);
        float wn = (wv - mu) / sigma;

        float b[NSPL];
#pragma unroll
        for (int s = 0; s < NSPL; s++) {
            float lo  = brk_s[s][0];
            float hib = brk_s[s][NINT] - 1e-6f;
            float wc  = fminf(fmaxf(wn, lo), hib);
            int kk = 0;
#pragma unroll
            for (int q = 1; q <= NINT; q++) kk += (brk_s[s][q] <= wc) ? 1 : 0;
            if (kk > NINT - 1) kk = NINT - 1;
            float t = wc - brk_s[s][kk];
            const float* a = &cf_s[(s * NINT + kk) * 4];
            b[s] = ((a[0] * t + a[1]) * t + a[2]) * t + a[3];
        }

        float rg = raw_gamma[o * IN_C + i];  // coalesced
        float g = fmaxf(rg, 0.0f) + log1pf(expf(-fabsf(rg)));
        g *= (1.0f / (float)OUT_C);

        const float LN2 = 0.69314718055994530942f;
        const float L2E = 1.44269504088896340736f;
        // scattered stores (fire-and-forget; ~4MB of L2 write sectors total)
        g_par4[i * OUT_C + o] = make_float4(b[2] * L2E, b[3], b[1] * LN2, b[0] * g * LN2);
        g_par1[i * OUT_C + o] = b[4] * g;
    } else {
        int wrp = threadIdx.x >> 5, lane = threadIdx.x & 31;
        int b = (blockIdx.x - 256) * 8 + wrp;
        const float* xb = x + b * IN_C;
        int cnt = 0;
#pragma unroll
        for (int h = 0; h < IN_C / 32; h++) {
            int il = h * 32 + lane;
            float xv = xb[il];
            bool act = xv > 0.0f;
            unsigned m = __ballot_sync(0xffffffffu, act);
            int pos = __popc(m & ((1u << lane) - 1));
            if (act) g_act[b * IN_C + cnt + pos] =
                         make_float2(xv, __int_as_float(il << 8));
            cnt += __popc(m);
        }
        int padded = (cnt + 7) & ~7;           // pad to 8 for unrolled main loop
        if (lane < padded - cnt)
            g_act[b * IN_C + cnt + lane] = make_float2(0.0f, __int_as_float(0));
        if (lane == 0) g_cnt[b] = padded;
    }
}

// Packed exp2 for a pair of chains: E{0,1} = 2^T{0,1}, T >= 0, f32x2 FMA path.
// Degree-5 poly on f in [-0.5,0.5]; abs err ~2.4e-6 (tolerance 1e-3).
#define EX2PAIR(T0, T1, E0, E1) do {                                        \
    ull _t2, _k2, _u2, _f2, _r2;                                            \
    asm("mov.b64 %0, {%1,%2};" : "=l"(_t2)                                  \
        : "r"(__float_as_uint(T0)), "r"(__float_as_uint(T1)));              \
    ADD2(_k2, _t2, cM2);                                                    \
    ADD2(_u2, _k2, cNM2);          /* k - MAGIC = round(t) */               \
    FMA2(_f2, _u2, cNONE2, _t2);   /* f = t - round(t), in [-0.5,0.5] */    \
    _r2 = cC1;                                                              \
    FMA2(_r2, _r2, _f2, cC2);                                               \
    FMA2(_r2, _r2, _f2, cC3);                                               \
    FMA2(_r2, _r2, _f2, cC4);                                               \
    FMA2(_r2, _r2, _f2, cC5);                                               \
    FMA2(_r2, _r2, _f2, cC6);                                               \
    unsigned _kl, _kh, _rl, _rh;                                            \
    asm("mov.b64 {%0,%1}, %2;" : "=r"(_kl), "=r"(_kh) : "l"(_k2));          \
    asm("mov.b64 {%0,%1}, %2;" : "=r"(_rl), "=r"(_rh) : "l"(_r2));          \
    (E0) = __uint_as_float(_rl + (_kl << 23));                              \
    (E1) = __uint_as_float(_rh + (_kh << 23));                              \
} while (0)

// Chain tail after e = exp(b3*x); zero-x padding contributes exactly 0:
// e=1 -> |e-1|=0 -> lg2=-inf -> ex2=0 -> lgA=0 -> lgB=0.
#define TAIL(XV, E, P, C5, A, B) do {                                       \
    float _lb = lg2f(fabsf((E) - 1.0f));                                    \
    float _pw = ex2f((P).y * _lb);                                          \
    float _lA = lg2f(_pw + 1.0f);                                           \
    float _lB = lg2f(fmaf((P).z, _lA, 1.0f));                               \
    (A) = fmaf((P).w, _lB, (A));                                            \
    (B) = fmaf((C5), (XV), (B));                                            \
} while (0)

// One pair of chains: param loads, t-pair, packed exp, tails.
#define PAIR(XA, IA, XB, IB, Aa, Ba, Ab, Bb) do {                           \
    int _ia = __float_as_int(IA), _ib = __float_as_int(IB);                 \
    float4 _Pa = __ldg(p4 + _ia);                                           \
    float4 _Pb = __ldg(p4 + _ib);                                           \
    float _ca = __ldg(p1 + _ia);                                            \
    float _cb = __ldg(p1 + _ib);                                            \
    float _ta = _Pa.x * (XA), _tb = _Pb.x * (XB);                           \
    float _ea, _eb;                                                         \
    EX2PAIR(_ta, _tb, _ea, _eb);                                            \
    TAIL((XA), _ea, _Pa, _ca, Aa, Ba);                                      \
    TAIL((XB), _eb, _Pb, _cb, Ab, Bb);                                      \
} while (0)

__global__ void __launch_bounds__(256)
kan_main(float* __restrict__ out) {
    int lane = threadIdx.x & 31;
    int wrp  = threadIdx.x >> 5;
    int b    = blockIdx.x * 8 + wrp;         // one batch per warp
    int o    = blockIdx.y * 32 + lane;       // one output per lane

    const float4* __restrict__ p4 = g_par4 + o;
    const float*  __restrict__ p1 = g_par1 + o;
    const float4* __restrict__ ap = (const float4*)(g_act + b * IN_C);

    const ull cM2    = pk2(12582912.0f);     // 1.5*2^23
    const ull cNM2   = pk2(-12582912.0f);
    const ull cNONE2 = pk2(-1.0f);
    const ull cC1    = pk2(1.33335581e-3f);
    const ull cC2    = pk2(9.61812911e-3f);
    const ull cC3    = pk2(5.55041087e-2f);
    const ull cC4    = pk2(2.40226507e-1f);
    const ull cC5    = pk2(6.93147181e-1f);
    const ull cC6    = pk2(1.0f);

    int cnt = g_cnt[b];                      // multiple of 8
    float A0 = 0.f, A1 = 0.f, A2 = 0.f, A3 = 0.f;
    float B0 = 0.f, B1 = 0.f, B2 = 0.f, B3 = 0.f;

    for (int n = 0; n < cnt; n += 8) {
        int h = n >> 1;
        float4 e01 = __ldg(ap + h);
        float4 e23 = __ldg(ap + h + 1);
        float4 e45 = __ldg(ap + h + 2);
        float4 e67 = __ldg(ap + h + 3);
        PAIR(e01.x, e01.y, e01.z, e01.w, A0, B0, A1, B1);
        PAIR(e23.x, e23.y, e23.z, e23.w, A2, B2, A3, B3);
        PAIR(e45.x, e45.y, e45.z, e45.w, A0, B0, A1, B1);
        PAIR(e67.x, e67.y, e67.z, e67.w, A2, B2, A3, B3);
    }

    float y  = ((A0 + A1) + (A2 + A3)) + ((B0 + B1) + (B2 + B3));
    float sp = fmaxf(y, 0.0f) + log1pf(expf(-fabsf(y)));
    out[b * OUT_C + o] = sp;
}

extern "C" void kernel_launch(void* const* d_in, const int* in_sizes, int n_in,
                              void* d_out, int out_size) {
    const float* x         = (const float*)d_in[0];
    const float* w         = (const float*)d_in[1];
    const float* raw_gamma = (const float*)d_in[2];
    const float* breaks    = (const float*)d_in[3];
    const float* coefs     = (const float*)d_in[4];
    const float* mu        = (const float*)d_in[5];
    const float* sigma     = (const float*)d_in[6];
    float* out = (float*)d_out;

    kan_pre<<<512, 256>>>(x, w, raw_gamma, breaks, coefs, mu, sigma);

    dim3 grid(BATCH / 8, OUT_C / 32);
    kan_main<<<grid, 256>>>(out);
}